// round 3
// baseline (speedup 1.0000x reference)
#include <cuda_runtime.h>

#define D 1024
#define H 8
#define MAX_T 16384
#define NEG_INF (-3.402823466e38f)

// Scratch for the input projection e[t][j] = (x @ W_ih^T)[t][j] + b_ih[j] + b_hh[j]
__device__ float g_e[MAX_T * H];

// ---------------------------------------------------------------------------
// Kernel 1: skinny GEMM  e[T,8] = x[T,1024] @ W_ih^T + (b_ih + b_hh)
// One warp per row t. W_ih staged in shared (32KB), x read coalesced float4.
// HBM-bound: reads 64MB of x exactly once.
// ---------------------------------------------------------------------------
__global__ __launch_bounds__(256)
void rnn_input_proj(const float* __restrict__ x,
                    const float* __restrict__ W_ih,
                    const float* __restrict__ b_ih,
                    const float* __restrict__ b_hh,
                    int T) {
    __shared__ float4 sW[H * (D / 4)];   // 8 * 256 float4 = 32KB
    __shared__ float  sb[H];

    int tid = threadIdx.x;
    for (int i = tid; i < H * (D / 4); i += blockDim.x)
        sW[i] = ((const float4*)W_ih)[i];
    if (tid < H) sb[tid] = b_ih[tid] + b_hh[tid];
    __syncthreads();

    int warp = tid >> 5, lane = tid & 31;
    int row = blockIdx.x * (blockDim.x >> 5) + warp;
    if (row >= T) return;

    const float4* xr = (const float4*)(x + (size_t)row * D);
    float acc[H];
#pragma unroll
    for (int j = 0; j < H; j++) acc[j] = 0.f;

#pragma unroll
    for (int i = 0; i < (D / 4) / 32; i++) {        // 8 iterations
        float4 xv = xr[lane + i * 32];
#pragma unroll
        for (int j = 0; j < H; j++) {
            float4 wv = sW[j * (D / 4) + lane + i * 32];
            acc[j] += xv.x * wv.x + xv.y * wv.y + xv.z * wv.z + xv.w * wv.w;
        }
    }

#pragma unroll
    for (int j = 0; j < H; j++) {
#pragma unroll
        for (int o = 16; o > 0; o >>= 1)
            acc[j] += __shfl_xor_sync(0xffffffffu, acc[j], o);
    }

    if (lane == 0) {
        float4 v0 = make_float4(acc[0] + sb[0], acc[1] + sb[1],
                                acc[2] + sb[2], acc[3] + sb[3]);
        float4 v1 = make_float4(acc[4] + sb[4], acc[5] + sb[5],
                                acc[6] + sb[6], acc[7] + sb[7]);
        float4* ep = (float4*)(g_e + (size_t)row * H);
        ep[0] = v0;
        ep[1] = v1;
    }
}

// ---------------------------------------------------------------------------
// Kernel 2: parallel scan of the relu recurrence + fused output projection.
//
// With diagonal, non-negative W_hh (diag d), each channel j independently obeys
//   h_t = max(d*h_{t-1} + e_t, 0)
// The affine-max maps  h -> max(c*h + a, b)  (c >= 0) are closed under
// composition:
//   (c1,a1,b1) then (c2,a2,b2)  =  (c1*c2, c2*a1 + a2, max(c2*b1 + a2, b2))
// identity = (1, 0, -inf). Associative => hierarchical scan:
//   per-thread serial aggregate over a chunk of 16 steps
//   -> warp inclusive scan (shfl)
//   -> cross-warp scan (warp 0)
//   -> each thread replays its chunk from the exclusive prefix and emits
//      out_t = h_t . W_out + b_out.
// A serial fallback (thread 0) covers non-diagonal / negative-diag W_hh.
// ---------------------------------------------------------------------------
__global__ __launch_bounds__(1024, 1)
void rnn_scan_out(const float* __restrict__ W_hh,
                  const float* __restrict__ W_out,
                  const float* __restrict__ b_out,
                  float* __restrict__ out, int T) {
    __shared__ float sd[H], swout[H], sWhh[H * H];
    __shared__ float sbout;
    __shared__ int   s_fb;
    __shared__ float wc[32][H], wa[32][H], wb[32][H];

    int tid = threadIdx.x;
    if (tid == 0) {
        int bad = 0;
        for (int i = 0; i < H; i++)
            for (int j = 0; j < H; j++) {
                float v = W_hh[i * H + j];
                sWhh[i * H + j] = v;
                if (i != j && v != 0.f) bad = 1;
            }
        for (int i = 0; i < H; i++) {
            float dv = sWhh[i * H + i];
            sd[i] = dv;
            if (!(dv >= 0.f)) bad = 1;   // need c >= 0 for max distribution
            swout[i] = W_out[i];
        }
        sbout = b_out[0];
        s_fb  = bad;
    }
    __syncthreads();

    if (s_fb) {
        // Correctness fallback: fully serial recurrence (never taken for the
        // dataset's identity W_hh; exists so the fast path is an optimization,
        // not an assumption).
        if (tid == 0) {
            float h[H];
            for (int j = 0; j < H; j++) h[j] = 0.f;
            for (int t = 0; t < T; t++) {
                float hn[H];
                for (int j = 0; j < H; j++) {
                    float s = g_e[(size_t)t * H + j];
                    for (int k = 0; k < H; k++) s += sWhh[j * H + k] * h[k];
                    hn[j] = fmaxf(s, 0.f);
                }
                float o = sbout;
                for (int j = 0; j < H; j++) { h[j] = hn[j]; o += h[j] * swout[j]; }
                out[t] = o;
            }
        }
        return;
    }

    const int nth   = blockDim.x;      // 1024
    const int chunk = T / nth;         // 16 for T=16384
    const int t0    = tid * chunk;
    const int lane  = tid & 31;
    const int wid   = tid >> 5;

    float d[H], c[H], a[H], b[H];
#pragma unroll
    for (int j = 0; j < H; j++) {
        d[j] = sd[j]; c[j] = 1.f; a[j] = 0.f; b[j] = NEG_INF;
    }

    // ---- pass 1: serial aggregate over this thread's chunk ----
    for (int k = 0; k < chunk; k++) {
        const float4* ep = (const float4*)(g_e + (size_t)(t0 + k) * H);
        float4 e0 = ep[0], e1 = ep[1];
        float ev[H] = {e0.x, e0.y, e0.z, e0.w, e1.x, e1.y, e1.z, e1.w};
#pragma unroll
        for (int j = 0; j < H; j++) {
            // compose current aggregate with step map (d, e, 0)
            c[j] = c[j] * d[j];
            a[j] = d[j] * a[j] + ev[j];
            b[j] = fmaxf(d[j] * b[j] + ev[j], 0.f);
        }
    }

    // ---- warp inclusive scan (Hillis-Steele, shfl_up) ----
#pragma unroll
    for (int off = 1; off < 32; off <<= 1) {
#pragma unroll
        for (int j = 0; j < H; j++) {
            float lc = __shfl_up_sync(0xffffffffu, c[j], off);
            float la = __shfl_up_sync(0xffffffffu, a[j], off);
            float lb = __shfl_up_sync(0xffffffffu, b[j], off);
            if (lane >= off) {
                // combine(left, mine): b' first (uses old a), then a', then c'
                b[j] = fmaxf(c[j] * lb + a[j], b[j]);
                a[j] = c[j] * la + a[j];
                c[j] = c[j] * lc;
            }
        }
    }

    if (lane == 31) {
#pragma unroll
        for (int j = 0; j < H; j++) {
            wc[wid][j] = c[j]; wa[wid][j] = a[j]; wb[wid][j] = b[j];
        }
    }
    __syncthreads();

    // ---- warp 0 scans the 32 warp aggregates ----
    if (wid == 0) {
        float cc[H], aa[H], bb[H];
#pragma unroll
        for (int j = 0; j < H; j++) {
            cc[j] = wc[lane][j]; aa[j] = wa[lane][j]; bb[j] = wb[lane][j];
        }
#pragma unroll
        for (int off = 1; off < 32; off <<= 1) {
#pragma unroll
            for (int j = 0; j < H; j++) {
                float lc = __shfl_up_sync(0xffffffffu, cc[j], off);
                float la = __shfl_up_sync(0xffffffffu, aa[j], off);
                float lb = __shfl_up_sync(0xffffffffu, bb[j], off);
                if (lane >= off) {
                    bb[j] = fmaxf(cc[j] * lb + aa[j], bb[j]);
                    aa[j] = cc[j] * la + aa[j];
                    cc[j] = cc[j] * lc;
                }
            }
        }
#pragma unroll
        for (int j = 0; j < H; j++) {
            wc[lane][j] = cc[j]; wa[lane][j] = aa[j]; wb[lane][j] = bb[j];
        }
    }
    __syncthreads();

    // ---- thread-exclusive prefix = combine(warp_prefix, lane_exclusive) ----
    float h[H];
#pragma unroll
    for (int j = 0; j < H; j++) {
        float lc = __shfl_up_sync(0xffffffffu, c[j], 1);
        float la = __shfl_up_sync(0xffffffffu, a[j], 1);
        float lb = __shfl_up_sync(0xffffffffu, b[j], 1);
        if (lane == 0) { lc = 1.f; la = 0.f; lb = NEG_INF; }

        float pc, pa, pb;
        if (wid > 0) { pc = wc[wid - 1][j]; pa = wa[wid - 1][j]; pb = wb[wid - 1][j]; }
        else         { pc = 1.f; pa = 0.f; pb = NEG_INF; }

        // excl = combine(prefix, lane_excl); apply to h0 = 0 -> max(a, b)
        float ea = lc * pa + la;
        float eb = fmaxf(lc * pb + la, lb);
        h[j] = fmaxf(ea, eb);
    }

    // ---- pass 2: replay chunk from h_in, emit fused output projection ----
    for (int k = 0; k < chunk; k++) {
        const float4* ep = (const float4*)(g_e + (size_t)(t0 + k) * H);
        float4 e0 = ep[0], e1 = ep[1];
        float ev[H] = {e0.x, e0.y, e0.z, e0.w, e1.x, e1.y, e1.z, e1.w};
        float o = sbout;
#pragma unroll
        for (int j = 0; j < H; j++) {
            h[j] = fmaxf(d[j] * h[j] + ev[j], 0.f);
            o += h[j] * swout[j];
        }
        out[t0 + k] = o;
    }
}

// ---------------------------------------------------------------------------
// kernel_launch: inputs in metadata order:
//   0: x [1,16384,1024] f32   1: W_ih [8,1024]  2: b_ih [8]
//   3: W_hh [8,8]             4: b_hh [8]       5: W_out [1,8]   6: b_out [1]
// output: [1,16384,1] f32
// ---------------------------------------------------------------------------
extern "C" void kernel_launch(void* const* d_in, const int* in_sizes, int n_in,
                              void* d_out, int out_size) {
    const float* x     = (const float*)d_in[0];
    const float* W_ih  = (const float*)d_in[1];
    const float* b_ih  = (const float*)d_in[2];
    const float* W_hh  = (const float*)d_in[3];
    const float* b_hh  = (const float*)d_in[4];
    const float* W_out = (const float*)d_in[5];
    const float* b_out = (const float*)d_in[6];
    float* out = (float*)d_out;

    int T = in_sizes[0] / D;   // 16384

    // 8 rows (warps) per 256-thread block
    rnn_input_proj<<<(T + 7) / 8, 256>>>(x, W_ih, b_ih, b_hh, T);
    rnn_scan_out<<<1, 1024>>>(W_hh, W_out, b_out, out, T);
}

// round 4
// speedup vs baseline: 2.0629x; 2.0629x over previous
#include <cuda_runtime.h>

#define D 1024
#define H 8
#define MAX_T 16384
#define RPW 4                      // rows per warp in K1
#define RPB 32                     // rows per block in K1 (8 warps * 4)
#define NCHUNK (MAX_T / RPB)       // 512 chunk aggregates
#define K3_ROWS 256                // rows per K3 block
#define NEG_INF (-3.402823466e38f)

// e[t][j] = (x @ W_ih^T)[t][j] + b_ih[j] + b_hh[j]
__device__ float g_e[MAX_T * H];
// per-chunk affine-max map aggregates and their inclusive scan: [chunk][{c,a,b}][H]
__device__ float g_agg [NCHUNK][3][H];
__device__ float g_pref[NCHUNK][3][H];

// ---------------------------------------------------------------------------
// K1: skinny GEMM e = x @ W_ih^T + bias, fused with per-chunk (32-row) scan
// aggregate. 8 warps/block, 4 rows/warp -> 32 contiguous rows per block.
// W staged once in smem; 4 rows amortize each W LDS (4x less LDS than 1 r/w).
// ---------------------------------------------------------------------------
__global__ __launch_bounds__(256)
void k1_proj_agg(const float* __restrict__ x,
                 const float* __restrict__ W_ih,
                 const float* __restrict__ b_ih,
                 const float* __restrict__ b_hh,
                 const float* __restrict__ W_hh,
                 int T) {
    __shared__ float4 sW[H * (D / 4)];       // 32KB
    __shared__ float  sb[H];
    __shared__ float  se[RPB][H];            // this block's e rows

    int tid = threadIdx.x;
    for (int i = tid; i < H * (D / 4); i += 256)
        sW[i] = ((const float4*)W_ih)[i];
    if (tid < H) sb[tid] = b_ih[tid] + b_hh[tid];
    __syncthreads();

    int warp = tid >> 5, lane = tid & 31;
    int row0 = blockIdx.x * RPB + warp * RPW;

    float acc[RPW][H];
#pragma unroll
    for (int r = 0; r < RPW; r++)
#pragma unroll
        for (int j = 0; j < H; j++) acc[r][j] = 0.f;

    const float4* xr = (const float4*)(x + (size_t)row0 * D);

#pragma unroll
    for (int i = 0; i < (D / 4) / 32; i++) {         // 8 iterations
        int col = lane + i * 32;
        float4 xv[RPW];
#pragma unroll
        for (int r = 0; r < RPW; r++) xv[r] = xr[r * (D / 4) + col];
#pragma unroll
        for (int j = 0; j < H; j++) {
            float4 wv = sW[j * (D / 4) + col];
#pragma unroll
            for (int r = 0; r < RPW; r++)
                acc[r][j] += xv[r].x * wv.x + xv[r].y * wv.y +
                             xv[r].z * wv.z + xv[r].w * wv.w;
        }
    }

    // butterfly reduce across lanes (all lanes end up with the row dots)
#pragma unroll
    for (int r = 0; r < RPW; r++)
#pragma unroll
        for (int j = 0; j < H; j++)
#pragma unroll
            for (int o = 16; o > 0; o >>= 1)
                acc[r][j] += __shfl_xor_sync(0xffffffffu, acc[r][j], o);

    if (lane == 0) {
#pragma unroll
        for (int r = 0; r < RPW; r++) {
            int row = row0 + r;
            if (row < T) {
                float4 v0 = make_float4(acc[r][0] + sb[0], acc[r][1] + sb[1],
                                        acc[r][2] + sb[2], acc[r][3] + sb[3]);
                float4 v1 = make_float4(acc[r][4] + sb[4], acc[r][5] + sb[5],
                                        acc[r][6] + sb[6], acc[r][7] + sb[7]);
                float4* ep = (float4*)(g_e + (size_t)row * H);
                ep[0] = v0; ep[1] = v1;
                se[warp * RPW + r][0] = v0.x; se[warp * RPW + r][1] = v0.y;
                se[warp * RPW + r][2] = v0.z; se[warp * RPW + r][3] = v0.w;
                se[warp * RPW + r][4] = v1.x; se[warp * RPW + r][5] = v1.y;
                se[warp * RPW + r][6] = v1.z; se[warp * RPW + r][7] = v1.w;
            }
        }
    }
    __syncthreads();

    // warp 0, lane j: serial-compose the 32 step maps (d_j, e, 0) for channel j
    if (warp == 0 && lane < H) {
        int j = lane;
        float dj = W_hh[j * H + j];
        float c = 1.f, a = 0.f, b = NEG_INF;
#pragma unroll
        for (int r = 0; r < RPB; r++) {
            float e = se[r][j];
            c = dj * c;
            a = dj * a + e;
            b = fmaxf(dj * b + e, 0.f);
        }
        g_agg[blockIdx.x][0][j] = c;
        g_agg[blockIdx.x][1][j] = a;
        g_agg[blockIdx.x][2][j] = b;
    }
}

// ---------------------------------------------------------------------------
// K2: single block scans the NCHUNK chunk aggregates -> inclusive prefixes.
// Also hosts the serial correctness fallback for non-diagonal/negative W_hh.
// ---------------------------------------------------------------------------
__global__ __launch_bounds__(512)
void k2_scan_agg(const float* __restrict__ W_hh,
                 const float* __restrict__ W_out,
                 const float* __restrict__ b_out,
                 float* __restrict__ out, int T) {
    __shared__ float wpc[16][H], wpa[16][H], wpb[16][H];
    __shared__ int   s_fb;

    int tid = threadIdx.x, lane = tid & 31, wid = tid >> 5;
    int nchunk = T / RPB;

    if (tid == 0) {
        int bad = 0;
        for (int i = 0; i < H; i++)
            for (int j = 0; j < H; j++)
                if (i != j && W_hh[i * H + j] != 0.f) bad = 1;
        for (int i = 0; i < H; i++)
            if (!(W_hh[i * H + i] >= 0.f)) bad = 1;
        s_fb = bad;
    }
    __syncthreads();

    if (s_fb) {
        // Serial fallback (never taken for identity W_hh): thread 0 does it all.
        if (tid == 0) {
            float h[H], Whh[H * H], wout[H];
            for (int i = 0; i < H * H; i++) Whh[i] = W_hh[i];
            for (int j = 0; j < H; j++) { h[j] = 0.f; wout[j] = W_out[j]; }
            float bo = b_out[0];
            for (int t = 0; t < T; t++) {
                float hn[H];
                for (int j = 0; j < H; j++) {
                    float s = g_e[(size_t)t * H + j];
                    for (int k = 0; k < H; k++) s += Whh[j * H + k] * h[k];
                    hn[j] = fmaxf(s, 0.f);
                }
                float o = bo;
                for (int j = 0; j < H; j++) { h[j] = hn[j]; o += h[j] * wout[j]; }
                out[t] = o;
            }
        }
        return;
    }

    float c[H], a[H], b[H];
    bool valid = tid < nchunk;
#pragma unroll
    for (int j = 0; j < H; j++) {
        c[j] = valid ? g_agg[tid][0][j] : 1.f;
        a[j] = valid ? g_agg[tid][1][j] : 0.f;
        b[j] = valid ? g_agg[tid][2][j] : NEG_INF;
    }

    // warp inclusive scan
#pragma unroll
    for (int off = 1; off < 32; off <<= 1) {
#pragma unroll
        for (int j = 0; j < H; j++) {
            float lc = __shfl_up_sync(0xffffffffu, c[j], off);
            float la = __shfl_up_sync(0xffffffffu, a[j], off);
            float lb = __shfl_up_sync(0xffffffffu, b[j], off);
            if (lane >= off) {
                b[j] = fmaxf(c[j] * lb + a[j], b[j]);
                a[j] = c[j] * la + a[j];
                c[j] = c[j] * lc;
            }
        }
    }
    if (lane == 31) {
#pragma unroll
        for (int j = 0; j < H; j++) {
            wpc[wid][j] = c[j]; wpa[wid][j] = a[j]; wpb[wid][j] = b[j];
        }
    }
    __syncthreads();

    // warp 0 scans the 16 warp aggregates
    if (wid == 0) {
        float cc[H], aa[H], bb[H];
        bool v = lane < 16;
#pragma unroll
        for (int j = 0; j < H; j++) {
            cc[j] = v ? wpc[lane][j] : 1.f;
            aa[j] = v ? wpa[lane][j] : 0.f;
            bb[j] = v ? wpb[lane][j] : NEG_INF;
        }
#pragma unroll
        for (int off = 1; off < 16; off <<= 1) {
#pragma unroll
            for (int j = 0; j < H; j++) {
                float lc = __shfl_up_sync(0xffffffffu, cc[j], off);
                float la = __shfl_up_sync(0xffffffffu, aa[j], off);
                float lb = __shfl_up_sync(0xffffffffu, bb[j], off);
                if (lane >= off) {
                    bb[j] = fmaxf(cc[j] * lb + aa[j], bb[j]);
                    aa[j] = cc[j] * la + aa[j];
                    cc[j] = cc[j] * lc;
                }
            }
        }
        if (v) {
#pragma unroll
            for (int j = 0; j < H; j++) {
                wpc[lane][j] = cc[j]; wpa[lane][j] = aa[j]; wpb[lane][j] = bb[j];
            }
        }
    }
    __syncthreads();

    if (wid > 0) {
#pragma unroll
        for (int j = 0; j < H; j++) {
            float pc = wpc[wid - 1][j], pa = wpa[wid - 1][j], pb = wpb[wid - 1][j];
            b[j] = fmaxf(c[j] * pb + a[j], b[j]);
            a[j] = c[j] * pa + a[j];
            c[j] = c[j] * pc;
        }
    }

    if (valid) {
#pragma unroll
        for (int j = 0; j < H; j++) {
            g_pref[tid][0][j] = c[j];
            g_pref[tid][1][j] = a[j];
            g_pref[tid][2][j] = b[j];
        }
    }
}

// ---------------------------------------------------------------------------
// K3: one thread per timestep. Block-level inclusive scan of step maps,
// seeded with the global chunk prefix; emits fused output projection.
// ---------------------------------------------------------------------------
__global__ __launch_bounds__(K3_ROWS)
void k3_apply(const float* __restrict__ W_hh,
              const float* __restrict__ W_out,
              const float* __restrict__ b_out,
              float* __restrict__ out, int T) {
    __shared__ float wpc[8][H], wpa[8][H], wpb[8][H];
    __shared__ int   s_fb;

    int tid = threadIdx.x, lane = tid & 31, wid = tid >> 5;

    if (tid == 0) {
        int bad = 0;
        for (int i = 0; i < H; i++)
            for (int j = 0; j < H; j++)
                if (i != j && W_hh[i * H + j] != 0.f) bad = 1;
        for (int i = 0; i < H; i++)
            if (!(W_hh[i * H + i] >= 0.f)) bad = 1;
        s_fb = bad;
    }
    __syncthreads();
    if (s_fb) return;   // K2 fallback already produced out

    int t = blockIdx.x * K3_ROWS + tid;
    bool valid = t < T;

    float d[H], wout[H];
#pragma unroll
    for (int j = 0; j < H; j++) { d[j] = W_hh[j * H + j]; wout[j] = W_out[j]; }

    float c[H], a[H], b[H];
    if (valid) {
        const float4* ep = (const float4*)(g_e + (size_t)t * H);
        float4 e0 = ep[0], e1 = ep[1];
        float ev[H] = {e0.x, e0.y, e0.z, e0.w, e1.x, e1.y, e1.z, e1.w};
#pragma unroll
        for (int j = 0; j < H; j++) { c[j] = d[j]; a[j] = ev[j]; b[j] = 0.f; }
    } else {
#pragma unroll
        for (int j = 0; j < H; j++) { c[j] = 1.f; a[j] = 0.f; b[j] = NEG_INF; }
    }

    // warp inclusive scan
#pragma unroll
    for (int off = 1; off < 32; off <<= 1) {
#pragma unroll
        for (int j = 0; j < H; j++) {
            float lc = __shfl_up_sync(0xffffffffu, c[j], off);
            float la = __shfl_up_sync(0xffffffffu, a[j], off);
            float lb = __shfl_up_sync(0xffffffffu, b[j], off);
            if (lane >= off) {
                b[j] = fmaxf(c[j] * lb + a[j], b[j]);
                a[j] = c[j] * la + a[j];
                c[j] = c[j] * lc;
            }
        }
    }
    if (lane == 31) {
#pragma unroll
        for (int j = 0; j < H; j++) {
            wpc[wid][j] = c[j]; wpa[wid][j] = a[j]; wpb[wid][j] = b[j];
        }
    }
    __syncthreads();

    // warp 0 scans the 8 warp aggregates
    if (wid == 0) {
        float cc[H], aa[H], bb[H];
        bool v = lane < (K3_ROWS / 32);
#pragma unroll
        for (int j = 0; j < H; j++) {
            cc[j] = v ? wpc[lane][j] : 1.f;
            aa[j] = v ? wpa[lane][j] : 0.f;
            bb[j] = v ? wpb[lane][j] : NEG_INF;
        }
#pragma unroll
        for (int off = 1; off < (K3_ROWS / 32); off <<= 1) {
#pragma unroll
            for (int j = 0; j < H; j++) {
                float lc = __shfl_up_sync(0xffffffffu, cc[j], off);
                float la = __shfl_up_sync(0xffffffffu, aa[j], off);
                float lb = __shfl_up_sync(0xffffffffu, bb[j], off);
                if (lane >= off) {
                    bb[j] = fmaxf(cc[j] * lb + aa[j], bb[j]);
                    aa[j] = cc[j] * la + aa[j];
                    cc[j] = cc[j] * lc;
                }
            }
        }
        if (v) {
#pragma unroll
            for (int j = 0; j < H; j++) {
                wpc[lane][j] = cc[j]; wpa[lane][j] = aa[j]; wpb[lane][j] = bb[j];
            }
        }
    }
    __syncthreads();

    if (wid > 0) {
#pragma unroll
        for (int j = 0; j < H; j++) {
            float pc = wpc[wid - 1][j], pa = wpa[wid - 1][j], pb = wpb[wid - 1][j];
            b[j] = fmaxf(c[j] * pb + a[j], b[j]);
            a[j] = c[j] * pa + a[j];
            c[j] = c[j] * pc;
        }
    }

    // global prefix: chunks [0, blockIdx*8) -> h at block entry
    float h_in[H];
    int pidx = blockIdx.x * (K3_ROWS / RPB) - 1;   // 8 chunks per K3 block
    if (pidx >= 0) {
#pragma unroll
        for (int j = 0; j < H; j++)
            h_in[j] = fmaxf(g_pref[pidx][1][j], g_pref[pidx][2][j]);  // apply to h0=0
    } else {
#pragma unroll
        for (int j = 0; j < H; j++) h_in[j] = 0.f;
    }

    if (valid) {
        float o = b_out[0];
#pragma unroll
        for (int j = 0; j < H; j++) {
            float h = fmaxf(c[j] * h_in[j] + a[j], b[j]);
            o += h * wout[j];
        }
        out[t] = o;
    }
}

// ---------------------------------------------------------------------------
// inputs: 0:x [1,T,1024] 1:W_ih[8,1024] 2:b_ih[8] 3:W_hh[8,8] 4:b_hh[8]
//         5:W_out[1,8]   6:b_out[1]      output: [1,T,1] f32
// ---------------------------------------------------------------------------
extern "C" void kernel_launch(void* const* d_in, const int* in_sizes, int n_in,
                              void* d_out, int out_size) {
    const float* x     = (const float*)d_in[0];
    const float* W_ih  = (const float*)d_in[1];
    const float* b_ih  = (const float*)d_in[2];
    const float* W_hh  = (const float*)d_in[3];
    const float* b_hh  = (const float*)d_in[4];
    const float* W_out = (const float*)d_in[5];
    const float* b_out = (const float*)d_in[6];
    float* out = (float*)d_out;

    int T = in_sizes[0] / D;   // 16384

    k1_proj_agg<<<(T + RPB - 1) / RPB, 256>>>(x, W_ih, b_ih, b_hh, W_hh, T);
    k2_scan_agg<<<1, 512>>>(W_hh, W_out, b_out, out, T);
    k3_apply<<<(T + K3_ROWS - 1) / K3_ROWS, K3_ROWS>>>(W_hh, W_out, b_out, out, T);
}

// round 5
// speedup vs baseline: 2.4841x; 1.2042x over previous
#include <cuda_runtime.h>
#include <cstdint>

#define D 1024
#define H 8
#define RPW 4                      // rows per warp in K1
#define RPB 32                     // rows per block in K1
#define NSTAGE 4                   // cp.async ring depth
#define CHUNK_F4 32                // float4 per row per column-chunk (128 floats)
#define NCH 8                      // column chunks (1024/128)
#define STAGE_FLOATS (RPB * 128)   // 4096 floats = 16KB per stage
#define B_ROWS 256                 // timesteps per apply-block
#define NEG_INF (-3.402823466e38f)

// e[t][j] = (x @ W_ih^T)[t][j] + b_ih[j] + b_hh[j]
__device__ float g_e[16384 * H];
// per-32-row-chunk affine-max aggregates: [chunk][{c,a,b}][H]
__device__ float g_agg[512][3][H];

// ---------------------------------------------------------------------------
// K1: skinny GEMM + per-chunk scan aggregate.
// x streamed via cp.async.cg (bypasses L1) through a 4-stage smem ring ->
// high MLP independent of occupancy. W_ih read via __ldg (L1-resident 32KB).
// ---------------------------------------------------------------------------
extern __shared__ float sx[];   // NSTAGE * STAGE_FLOATS = 64KB

__device__ __forceinline__ void k1_issue_stage(const float4* xbase, int i, int tid) {
    int s = i & (NSTAGE - 1);
#pragma unroll
    for (int k = 0; k < 4; k++) {
        int q   = k * 256 + tid;          // 0..1023
        int row = q >> 5;                 // 0..31
        int sub = q & 31;                 // float4 within chunk
        const float4* src = xbase + (size_t)row * (D / 4) + i * CHUNK_F4 + sub;
        uint32_t dst = (uint32_t)__cvta_generic_to_shared(
            sx + s * STAGE_FLOATS + row * 128 + sub * 4);
        asm volatile("cp.async.cg.shared.global [%0], [%1], 16;\n"
                     :: "r"(dst), "l"(src));
    }
    asm volatile("cp.async.commit_group;\n");
}

__global__ __launch_bounds__(256)
void k1_proj_agg(const float* __restrict__ x,
                 const float* __restrict__ W_ih,
                 const float* __restrict__ b_ih,
                 const float* __restrict__ b_hh,
                 const float* __restrict__ W_hh,
                 int T) {
    __shared__ float se[RPB][H];
    __shared__ float sb[H];

    int tid  = threadIdx.x;
    int warp = tid >> 5, lane = tid & 31;
    int row0 = blockIdx.x * RPB;

    if (tid < H) sb[tid] = b_ih[tid] + b_hh[tid];

    const float4* xbase = (const float4*)(x + (size_t)row0 * D);
    const float4* Wv    = (const float4*)W_ih;

    // prologue: fill the ring
#pragma unroll
    for (int i = 0; i < NSTAGE; i++) k1_issue_stage(xbase, i, tid);

    float acc[RPW][H];
#pragma unroll
    for (int r = 0; r < RPW; r++)
#pragma unroll
        for (int j = 0; j < H; j++) acc[r][j] = 0.f;

#pragma unroll
    for (int i = 0; i < NCH; i++) {
        asm volatile("cp.async.wait_group %0;\n" :: "n"(NSTAGE - 1));
        __syncthreads();
        int s = i & (NSTAGE - 1);

        float4 xv[RPW];
#pragma unroll
        for (int r = 0; r < RPW; r++)
            xv[r] = *(const float4*)(sx + s * STAGE_FLOATS +
                                     (warp * RPW + r) * 128 + lane * 4);
#pragma unroll
        for (int j = 0; j < H; j++) {
            float4 wv = __ldg(Wv + (size_t)j * (D / 4) + i * CHUNK_F4 + lane);
#pragma unroll
            for (int r = 0; r < RPW; r++)
                acc[r][j] += xv[r].x * wv.x + xv[r].y * wv.y +
                             xv[r].z * wv.z + xv[r].w * wv.w;
        }
        __syncthreads();
        if (i + NSTAGE < NCH) k1_issue_stage(xbase, i + NSTAGE, tid);
        else asm volatile("cp.async.commit_group;\n");  // keep group count uniform
    }

    // butterfly reduce across lanes
#pragma unroll
    for (int r = 0; r < RPW; r++)
#pragma unroll
        for (int j = 0; j < H; j++)
#pragma unroll
            for (int o = 16; o > 0; o >>= 1)
                acc[r][j] += __shfl_xor_sync(0xffffffffu, acc[r][j], o);

    if (lane == 0) {
#pragma unroll
        for (int r = 0; r < RPW; r++) {
            int row = row0 + warp * RPW + r;
            if (row < T) {
                float4 v0 = make_float4(acc[r][0] + sb[0], acc[r][1] + sb[1],
                                        acc[r][2] + sb[2], acc[r][3] + sb[3]);
                float4 v1 = make_float4(acc[r][4] + sb[4], acc[r][5] + sb[5],
                                        acc[r][6] + sb[6], acc[r][7] + sb[7]);
                float4* ep = (float4*)(g_e + (size_t)row * H);
                ep[0] = v0; ep[1] = v1;
                int lr = warp * RPW + r;
                se[lr][0] = v0.x; se[lr][1] = v0.y; se[lr][2] = v0.z; se[lr][3] = v0.w;
                se[lr][4] = v1.x; se[lr][5] = v1.y; se[lr][6] = v1.z; se[lr][7] = v1.w;
            }
        }
    }
    __syncthreads();

    // warp 0, lane j: compose the 32 step maps (d_j, e, 0) for channel j
    if (warp == 0 && lane < H) {
        int j = lane;
        float dj = W_hh[j * H + j];
        float c = 1.f, a = 0.f, b = NEG_INF;
#pragma unroll
        for (int r = 0; r < RPB; r++) {
            float e = se[r][j];
            c = dj * c;
            a = dj * a + e;
            b = fmaxf(dj * b + e, 0.f);
        }
        g_agg[blockIdx.x][0][j] = c;
        g_agg[blockIdx.x][1][j] = a;
        g_agg[blockIdx.x][2][j] = b;
    }
}

// ---------------------------------------------------------------------------
// KB: fused global scan + apply. Each block (256 threads, 256 timesteps):
//  phase 1: pair-compose the T/32 chunk aggregates (-> <=256 elems), block
//           inclusive scan, extract the prefix map ending at this block's
//           entry (chunk index 8*bid - 1 == pair index 4*bid - 1).
//  phase 2: per-thread step map from g_e, block scan seeded by that prefix,
//           fused output projection.
// Serial fallback (non-diagonal / negative-diag W_hh) runs in block 0.
// ---------------------------------------------------------------------------
__global__ __launch_bounds__(B_ROWS)
void kb_scan_apply(const float* __restrict__ W_hh,
                   const float* __restrict__ W_out,
                   const float* __restrict__ b_out,
                   float* __restrict__ out, int T) {
    __shared__ float wpc[8][H], wpa[8][H], wpb[8][H];
    __shared__ float spa[H], spb[H];     // block-entry prefix (a, b)
    __shared__ int   s_fb;

    int tid = threadIdx.x, lane = tid & 31, wid = tid >> 5;

    if (tid == 0) {
        int bad = 0;
        for (int i = 0; i < H; i++)
            for (int j = 0; j < H; j++)
                if (i != j && W_hh[i * H + j] != 0.f) bad = 1;
        for (int i = 0; i < H; i++)
            if (!(W_hh[i * H + i] >= 0.f)) bad = 1;
        s_fb = bad;
    }
    __syncthreads();

    if (s_fb) {
        // Correctness fallback (never taken for identity W_hh).
        if (blockIdx.x == 0 && tid == 0) {
            float h[H], Whh[H * H], wout[H];
            for (int i = 0; i < H * H; i++) Whh[i] = W_hh[i];
            for (int j = 0; j < H; j++) { h[j] = 0.f; wout[j] = W_out[j]; }
            float bo = b_out[0];
            for (int t = 0; t < T; t++) {
                float hn[H];
                for (int j = 0; j < H; j++) {
                    float s = g_e[(size_t)t * H + j];
                    for (int k = 0; k < H; k++) s += Whh[j * H + k] * h[k];
                    hn[j] = fmaxf(s, 0.f);
                }
                float o = bo;
                for (int j = 0; j < H; j++) { h[j] = hn[j]; o += h[j] * wout[j]; }
                out[t] = o;
            }
        }
        return;
    }

    // ---------------- phase 1: aggregate scan ----------------
    int nchunk = T / RPB;
    int npair  = (nchunk + 1) >> 1;
    int eidx   = (int)blockIdx.x * 4 - 1;   // needed inclusive pair index
    {
        float c[H], a[H], b[H];
        bool v = tid < npair;
        if (v) {
            int i0 = 2 * tid, i1 = 2 * tid + 1;
#pragma unroll
            for (int j = 0; j < H; j++) {
                float c0 = g_agg[i0][0][j], a0 = g_agg[i0][1][j], b0 = g_agg[i0][2][j];
                if (i1 < nchunk) {
                    float c1 = g_agg[i1][0][j], a1 = g_agg[i1][1][j], b1 = g_agg[i1][2][j];
                    c[j] = c0 * c1;
                    a[j] = c1 * a0 + a1;
                    b[j] = fmaxf(c1 * b0 + a1, b1);
                } else { c[j] = c0; a[j] = a0; b[j] = b0; }
            }
        } else {
#pragma unroll
            for (int j = 0; j < H; j++) { c[j] = 1.f; a[j] = 0.f; b[j] = NEG_INF; }
        }

#pragma unroll
        for (int off = 1; off < 32; off <<= 1) {
#pragma unroll
            for (int j = 0; j < H; j++) {
                float lc = __shfl_up_sync(0xffffffffu, c[j], off);
                float la = __shfl_up_sync(0xffffffffu, a[j], off);
                float lb = __shfl_up_sync(0xffffffffu, b[j], off);
                if (lane >= off) {
                    b[j] = fmaxf(c[j] * lb + a[j], b[j]);
                    a[j] = c[j] * la + a[j];
                    c[j] = c[j] * lc;
                }
            }
        }
        if (lane == 31) {
#pragma unroll
            for (int j = 0; j < H; j++) {
                wpc[wid][j] = c[j]; wpa[wid][j] = a[j]; wpb[wid][j] = b[j];
            }
        }
        __syncthreads();
        if (wid == 0) {
            float cc[H], aa[H], bb[H];
            bool v8 = lane < 8;
#pragma unroll
            for (int j = 0; j < H; j++) {
                cc[j] = v8 ? wpc[lane][j] : 1.f;
                aa[j] = v8 ? wpa[lane][j] : 0.f;
                bb[j] = v8 ? wpb[lane][j] : NEG_INF;
            }
#pragma unroll
            for (int off = 1; off < 8; off <<= 1) {
#pragma unroll
                for (int j = 0; j < H; j++) {
                    float lc = __shfl_up_sync(0xffffffffu, cc[j], off);
                    float la = __shfl_up_sync(0xffffffffu, aa[j], off);
                    float lb = __shfl_up_sync(0xffffffffu, bb[j], off);
                    if (lane >= off) {
                        bb[j] = fmaxf(cc[j] * lb + aa[j], bb[j]);
                        aa[j] = cc[j] * la + aa[j];
                        cc[j] = cc[j] * lc;
                    }
                }
            }
            if (v8) {
#pragma unroll
                for (int j = 0; j < H; j++) {
                    wpc[lane][j] = cc[j]; wpa[lane][j] = aa[j]; wpb[lane][j] = bb[j];
                }
            }
        }
        __syncthreads();

        if (eidx < 0) {
            if (tid == 0)
#pragma unroll
                for (int j = 0; j < H; j++) { spa[j] = 0.f; spb[j] = NEG_INF; }
        } else if (tid == eidx) {
#pragma unroll
            for (int j = 0; j < H; j++) {
                float aj = a[j], bj = b[j], cj = c[j];
                if (wid > 0) {
                    float pa = wpa[wid - 1][j], pb = wpb[wid - 1][j];
                    bj = fmaxf(cj * pb + aj, bj);
                    aj = cj * pa + aj;
                }
                spa[j] = aj; spb[j] = bj;
            }
        }
    }
    __syncthreads();

    float h_in[H];
#pragma unroll
    for (int j = 0; j < H; j++) h_in[j] = fmaxf(spa[j], spb[j]);  // apply to h0=0

    // ---------------- phase 2: per-timestep scan + output ----------------
    int t = blockIdx.x * B_ROWS + tid;
    bool valid = t < T;

    float d[H], wout[H];
#pragma unroll
    for (int j = 0; j < H; j++) { d[j] = W_hh[j * H + j]; wout[j] = W_out[j]; }

    float c[H], a[H], b[H];
    if (valid) {
        const float4* ep = (const float4*)(g_e + (size_t)t * H);
        float4 e0 = ep[0], e1 = ep[1];
        float ev[H] = {e0.x, e0.y, e0.z, e0.w, e1.x, e1.y, e1.z, e1.w};
#pragma unroll
        for (int j = 0; j < H; j++) { c[j] = d[j]; a[j] = ev[j]; b[j] = 0.f; }
    } else {
#pragma unroll
        for (int j = 0; j < H; j++) { c[j] = 1.f; a[j] = 0.f; b[j] = NEG_INF; }
    }

#pragma unroll
    for (int off = 1; off < 32; off <<= 1) {
#pragma unroll
        for (int j = 0; j < H; j++) {
            float lc = __shfl_up_sync(0xffffffffu, c[j], off);
            float la = __shfl_up_sync(0xffffffffu, a[j], off);
            float lb = __shfl_up_sync(0xffffffffu, b[j], off);
            if (lane >= off) {
                b[j] = fmaxf(c[j] * lb + a[j], b[j]);
                a[j] = c[j] * la + a[j];
                c[j] = c[j] * lc;
            }
        }
    }
    if (lane == 31) {
#pragma unroll
        for (int j = 0; j < H; j++) {
            wpc[wid][j] = c[j]; wpa[wid][j] = a[j]; wpb[wid][j] = b[j];
        }
    }
    __syncthreads();
    if (wid == 0) {
        float cc[H], aa[H], bb[H];
        bool v8 = lane < 8;
#pragma unroll
        for (int j = 0; j < H; j++) {
            cc[j] = v8 ? wpc[lane][j] : 1.f;
            aa[j] = v8 ? wpa[lane][j] : 0.f;
            bb[j] = v8 ? wpb[lane][j] : NEG_INF;
        }
#pragma unroll
        for (int off = 1; off < 8; off <<= 1) {
#pragma unroll
            for (int j = 0; j < H; j++) {
                float lc = __shfl_up_sync(0xffffffffu, cc[j], off);
                float la = __shfl_up_sync(0xffffffffu, aa[j], off);
                float lb = __shfl_up_sync(0xffffffffu, bb[j], off);
                if (lane >= off) {
                    bb[j] = fmaxf(cc[j] * lb + aa[j], bb[j]);
                    aa[j] = cc[j] * la + aa[j];
                    cc[j] = cc[j] * lc;
                }
            }
        }
        if (v8) {
#pragma unroll
            for (int j = 0; j < H; j++) {
                wpc[lane][j] = cc[j]; wpa[lane][j] = aa[j]; wpb[lane][j] = bb[j];
            }
        }
    }
    __syncthreads();

    if (wid > 0) {
#pragma unroll
        for (int j = 0; j < H; j++) {
            float pc = wpc[wid - 1][j], pa = wpa[wid - 1][j], pb = wpb[wid - 1][j];
            b[j] = fmaxf(c[j] * pb + a[j], b[j]);
            a[j] = c[j] * pa + a[j];
            c[j] = c[j] * pc;
        }
    }

    if (valid) {
        float o = b_out[0];
#pragma unroll
        for (int j = 0; j < H; j++) {
            float h = fmaxf(c[j] * h_in[j] + a[j], b[j]);
            o += h * wout[j];
        }
        out[t] = o;
    }
}

// ---------------------------------------------------------------------------
// inputs: 0:x [1,T,1024] 1:W_ih[8,1024] 2:b_ih[8] 3:W_hh[8,8] 4:b_hh[8]
//         5:W_out[1,8]   6:b_out[1]      output: [1,T,1] f32
// ---------------------------------------------------------------------------
extern "C" void kernel_launch(void* const* d_in, const int* in_sizes, int n_in,
                              void* d_out, int out_size) {
    const float* x     = (const float*)d_in[0];
    const float* W_ih  = (const float*)d_in[1];
    const float* b_ih  = (const float*)d_in[2];
    const float* W_hh  = (const float*)d_in[3];
    const float* b_hh  = (const float*)d_in[4];
    const float* W_out = (const float*)d_in[5];
    const float* b_out = (const float*)d_in[6];
    float* out = (float*)d_out;

    int T = in_sizes[0] / D;   // 16384
    int smem = NSTAGE * STAGE_FLOATS * sizeof(float);   // 64KB

    cudaFuncSetAttribute(k1_proj_agg,
                         cudaFuncAttributeMaxDynamicSharedMemorySize, smem);

    k1_proj_agg<<<(T + RPB - 1) / RPB, 256, smem>>>(x, W_ih, b_ih, b_hh, W_hh, T);
    kb_scan_apply<<<(T + B_ROWS - 1) / B_ROWS, B_ROWS>>>(W_hh, W_out, b_out, out, T);
}